// round 15
// baseline (speedup 1.0000x reference)
#include <cuda_runtime.h>
#include <cuda_bf16.h>
#include <cstdint>

#define Bq   4
#define SEQ  2048
#define CH   768
#define NH   8
#define HDIM 96
#define MTOT (Bq*SEQ)     /* 8192 */
#define N1   (3*CH)       /* 2304 */

// ---- HMMA helpers (baseline PTX, sm_80+) -------------------------------------
__device__ __forceinline__ uint32_t smem_u32(const void* p) {
    uint32_t a;
    asm("{ .reg .u64 t; cvta.to.shared.u64 t, %1; cvt.u32.u64 %0, t; }" : "=r"(a) : "l"(p));
    return a;
}
__device__ __forceinline__ void ldsm4(uint32_t* r, uint32_t addr) {
    asm volatile("ldmatrix.sync.aligned.m8n8.x4.shared.b16 {%0,%1,%2,%3}, [%4];"
        : "=r"(r[0]), "=r"(r[1]), "=r"(r[2]), "=r"(r[3]) : "r"(addr));
}
__device__ __forceinline__ void ldsm4t(uint32_t* r, uint32_t addr) {
    asm volatile("ldmatrix.sync.aligned.m8n8.x4.trans.shared.b16 {%0,%1,%2,%3}, [%4];"
        : "=r"(r[0]), "=r"(r[1]), "=r"(r[2]), "=r"(r[3]) : "r"(addr));
}
__device__ __forceinline__ void mma_bf16(float* d, const uint32_t* a, const uint32_t* b) {
    asm volatile("mma.sync.aligned.m16n8k16.row.col.f32.bf16.bf16.f32 "
        "{%0,%1,%2,%3}, {%4,%5,%6,%7}, {%8,%9}, {%0,%1,%2,%3};"
        : "+f"(d[0]), "+f"(d[1]), "+f"(d[2]), "+f"(d[3])
        : "r"(a[0]), "r"(a[1]), "r"(a[2]), "r"(a[3]), "r"(b[0]), "r"(b[1]));
}
__device__ __forceinline__ uint32_t hi_pair(float x, float y) {
    return __byte_perm(__float_as_uint(x), __float_as_uint(y), 0x7632);
}
__device__ __forceinline__ uint32_t lo_pair(float x, float y) {
    float lx = x - __uint_as_float(__float_as_uint(x) & 0xffff0000u);
    float ly = y - __uint_as_float(__float_as_uint(y) & 0xffff0000u);
    uint32_t r;
    asm("cvt.rn.bf16x2.f32 %0, %1, %2;" : "=r"(r) : "f"(ly), "f"(lx));
    return r;
}
__device__ __forceinline__ float ex2(float x) {
    float y; asm("ex2.approx.f32 %0, %1;" : "=f"(y) : "f"(x)); return y;
}
// ---- cp.async -----------------------------------------------------------------
__device__ __forceinline__ void cp16(uint32_t saddr, const void* g) {
    asm volatile("cp.async.cg.shared.global [%0], [%1], 16;" :: "r"(saddr), "l"(g));
}
__device__ __forceinline__ void cp_commit() { asm volatile("cp.async.commit_group;" ::: "memory"); }
template<int N> __device__ __forceinline__ void cp_wait() {
    asm volatile("cp.async.wait_group %0;" :: "n"(N) : "memory");
}

// ---------------- scratch (static __device__, no allocations) ----------------
__device__ __nv_bfloat16 g_xh[(size_t)MTOT*CH],  g_xl[(size_t)MTOT*CH];
__device__ __nv_bfloat16 g_wqh[(size_t)N1*CH],   g_wql[(size_t)N1*CH];
__device__ __nv_bfloat16 g_wph[(size_t)CH*CH],   g_wpl[(size_t)CH*CH];
__device__ __nv_bfloat16 g_qh[(size_t)Bq*NH*SEQ*HDIM];
__device__ __nv_bfloat16 g_ql[(size_t)Bq*NH*SEQ*HDIM];
__device__ __nv_bfloat16 g_kh[(size_t)Bq*NH*SEQ*HDIM];
__device__ __nv_bfloat16 g_kl[(size_t)Bq*NH*SEQ*HDIM];
__device__ __nv_bfloat16 g_vh[(size_t)Bq*NH*SEQ*HDIM];
__device__ __nv_bfloat16 g_vl[(size_t)Bq*NH*SEQ*HDIM];
__device__ __nv_bfloat16 g_ch[(size_t)MTOT*CH],  g_cl[(size_t)MTOT*CH];

// ---------------- split inputs once: fp32 -> bf16 hi/lo ----------------------
__global__ void split_all(const float* __restrict__ x,
                          const float* __restrict__ wq,
                          const float* __restrict__ wp)
{
    const int NX = MTOT*CH/4, NQ = N1*CH/4, NP = CH*CH/4;
    int i = blockIdx.x * blockDim.x + threadIdx.x;
    const float* src; __nv_bfloat16 *dh, *dl; int j;
    if (i < NX)                { src = x;  dh = g_xh;  dl = g_xl;  j = i; }
    else if (i < NX + NQ)      { src = wq; dh = g_wqh; dl = g_wql; j = i - NX; }
    else if (i < NX + NQ + NP) { src = wp; dh = g_wph; dl = g_wpl; j = i - NX - NQ; }
    else return;
    float4 v = ((const float4*)src)[j];
    uint2 hi = make_uint2(hi_pair(v.x, v.y), hi_pair(v.z, v.w));
    uint2 lo = make_uint2(lo_pair(v.x, v.y), lo_pair(v.z, v.w));
    ((uint2*)dh)[j] = hi;
    ((uint2*)dl)[j] = lo;
}

// ---------------- bf16-input HMMA NT GEMM, cp.async 3-stage, occ 2 ------------
__device__ __forceinline__ uint32_t swz(int r, int c) {   // byte offset of 16B chunk
    return (uint32_t)(r * 64 + ((c ^ ((r >> 1) & 3)) << 4));
}

template<int EPI, int BN>
__global__ __launch_bounds__(256, 2) void gemm_bf16(const __nv_bfloat16* __restrict__ Ah_g,
                                                    const __nv_bfloat16* __restrict__ Al_g,
                                                    const __nv_bfloat16* __restrict__ Bh_g,
                                                    const __nv_bfloat16* __restrict__ Bl_g,
                                                    const float* __restrict__ aux0,   // cos | bias
                                                    const float* __restrict__ aux1,   // sin | null
                                                    float* __restrict__ Cmat,
                                                    int Ntot, int Ktot)
{
    constexpr uint32_t AH = 0, AL = 8192, BH = 16384;
    constexpr uint32_t BL = BH + (uint32_t)BN * 64;
    constexpr uint32_t STAGE = BH + 2u * (uint32_t)BN * 64;
    constexpr int NJ = BN / 16;

    extern __shared__ __align__(128) char smem[];
    const uint32_t sb = smem_u32(smem);
    const int tid = threadIdx.x, wid = tid >> 5, lane = tid & 31;
    const int wm = (wid & 3) * 32;
    const int wn = (wid >> 2) * (BN / 2);
    const int m0 = blockIdx.y * 128, n0 = blockIdx.x * BN;

    float acc[2][NJ][4];
#pragma unroll
    for (int t = 0; t < 2; t++)
#pragma unroll
        for (int j = 0; j < NJ; j++)
#pragma unroll
            for (int q = 0; q < 4; q++) acc[t][j][q] = 0.f;

    const int NIT = Ktot >> 5;   // 24
    const int chR = tid >> 2, chC = tid & 3;

    auto produce = [&](int it) {
        const uint32_t base = sb + (uint32_t)(it % 3) * STAGE;
        const int k0 = it << 5;
#pragma unroll
        for (int u = 0; u < 2; u++) {
            int r = chR + u * 64;
            uint32_t sw = swz(r, chC);
            size_t goA = (size_t)(m0 + r) * Ktot + k0 + chC * 8;
            cp16(base + AH + sw, Ah_g + goA);
            cp16(base + AL + sw, Al_g + goA);
        }
#pragma unroll
        for (int v = 0; v < BN / 64; v++) {
            int r = chR + v * 64;
            uint32_t sw = swz(r, chC);
            size_t goB = (size_t)(n0 + r) * Ktot + k0 + chC * 8;
            cp16(base + BH + sw, Bh_g + goB);
            cp16(base + BL + sw, Bl_g + goB);
        }
        cp_commit();
    };

    const int lrow = lane & 15, lgrp = lane >> 4;

    auto compute = [&](int stg) {
        const uint32_t base = sb + (uint32_t)stg * STAGE;
#pragma unroll
        for (int ks = 0; ks < 2; ks++) {
            const int c = 2 * ks + lgrp;
            uint32_t Ahf[2][4], Alf[2][4];
#pragma unroll
            for (int t = 0; t < 2; t++) {
                int r = wm + t * 16 + lrow;
                uint32_t sw = swz(r, c);
                ldsm4(Ahf[t], base + AH + sw);
                ldsm4(Alf[t], base + AL + sw);
            }
#pragma unroll
            for (int ng = 0; ng < BN / 32; ng++) {
                int r = wn + ng * 16 + lrow;
                uint32_t sw = swz(r, c);
                uint32_t Bh4[4], Bl4[4];
                ldsm4(Bh4, base + BH + sw);
                ldsm4(Bl4, base + BL + sw);
                uint32_t bh0[2] = {Bh4[0], Bh4[2]}, bh1[2] = {Bh4[1], Bh4[3]};
                uint32_t bl0[2] = {Bl4[0], Bl4[2]}, bl1[2] = {Bl4[1], Bl4[3]};
#pragma unroll
                for (int t = 0; t < 2; t++) {
                    mma_bf16(acc[t][2*ng],   Ahf[t], bh0);
                    mma_bf16(acc[t][2*ng],   Ahf[t], bl0);
                    mma_bf16(acc[t][2*ng],   Alf[t], bh0);
                    mma_bf16(acc[t][2*ng+1], Ahf[t], bh1);
                    mma_bf16(acc[t][2*ng+1], Ahf[t], bl1);
                    mma_bf16(acc[t][2*ng+1], Alf[t], bh1);
                }
            }
        }
    };

    produce(0); produce(1);
    for (int it = 0; it < NIT; it++) {
        cp_wait<1>();
        __syncthreads();
        if (it + 2 < NIT) produce(it + 2);
        compute(it % 3);
    }

    // ---- epilogue ----
    if (EPI == 1) {
#pragma unroll
        for (int t = 0; t < 2; t++) {
            const int row0 = m0 + wm + t*16 + (lane >> 2);
#pragma unroll
            for (int j = 0; j < NJ; j++) {
                const int col = n0 + wn + j*8 + (lane & 3)*2;
                float b0 = aux0[col], b1 = aux0[col+1];
                *(float2*)(Cmat + (size_t)row0 * Ntot + col) =
                    make_float2(acc[t][j][0] + b0, acc[t][j][1] + b1);
                *(float2*)(Cmat + (size_t)(row0+8) * Ntot + col) =
                    make_float2(acc[t][j][2] + b0, acc[t][j][3] + b1);
            }
        }
    } else {
        // q pre-scale folds HD^-0.5 AND log2(e) so flash can use raw ex2
        const float qscale = 0.10206207261596575f * 1.4426950408889634f;
#pragma unroll
        for (int t = 0; t < 2; t++) {
            const int rowA = m0 + wm + t*16 + (lane >> 2);
#pragma unroll
            for (int j = 0; j < NJ; j++) {
                const int col = n0 + wn + j*8 + (lane & 3)*2;   // even
                const int which = col / CH;
                const int cc = col - which * CH;
                const int h = cc / HDIM;
                const int d = cc - h * HDIM;
#pragma unroll
                for (int half = 0; half < 2; half++) {
                    const int m = rowA + half * 8;
                    const int s = m & (SEQ - 1), b = m >> 11;
                    float e = acc[t][j][2*half], o = acc[t][j][2*half+1];
                    float2 y;
                    if (which == 2) {
                        y = make_float2(e, o);
                    } else {
                        float cs = aux0[s * HDIM + d];
                        float sn = aux1[s * HDIM + d];
                        y.x = e * cs - o * sn;
                        y.y = o * cs + e * sn;
                        if (which == 0) { y.x *= qscale; y.y *= qscale; }
                    }
                    size_t off = ((size_t)(b * NH + h) * SEQ + s) * HDIM + d;
                    uint32_t hi = hi_pair(y.x, y.y);
                    uint32_t lo = lo_pair(y.x, y.y);
                    __nv_bfloat16* dh = (which == 0) ? g_qh : (which == 1) ? g_kh : g_vh;
                    __nv_bfloat16* dl = (which == 0) ? g_ql : (which == 1) ? g_kl : g_vl;
                    *(uint32_t*)(dh + off) = hi;
                    *(uint32_t*)(dl + off) = lo;
                }
            }
        }
    }
}

// ---------------- flash attention: BM=64, BN=64, 4 warps, 2 CTAs/SM -----------
// R12 structure + lane-partial l (quad-reduced once in epilogue).
#define RS   208u
#define BSZ  13312u
#define STG  53248u
#define NTT  32
__global__ __launch_bounds__(128, 2) void flash_hmma()
{
    extern __shared__ __align__(128) char sm[];
    const uint32_t sb = smem_u32(sm);

    const int tid = threadIdx.x, wid = tid >> 5, lane = tid & 31;
    const int bh = blockIdx.y;
    const int q0 = blockIdx.x * 64;
    const float NEG_INF = __int_as_float(0xff800000);

    const uint32_t lrow = (uint32_t)(lane & 15);
    const uint32_t lgrp = (uint32_t)(lane >> 4);

    // ---- stage Q (64 rows) into stage-0 area, ldsm to registers ----
    uint32_t qH[6][4], qL[6][4];
    {
        const char* qh = (const char*)(g_qh + ((size_t)bh * SEQ + q0) * HDIM);
        const char* ql = (const char*)(g_ql + ((size_t)bh * SEQ + q0) * HDIM);
#pragma unroll
        for (int i = 0; i < 6; i++) {
            int idx = tid + i * 128;
            int r = idx / 12, g = idx % 12;
            uint32_t so = (uint32_t)r * RS + (uint32_t)g * 16u;
            *(uint4*)(sm + so)          = *(const uint4*)(qh + r * 192 + g * 16);
            *(uint4*)(sm + 26624u + so) = *(const uint4*)(ql + r * 192 + g * 16);
        }
        __syncthreads();
        const uint32_t aOff = ((uint32_t)(wid * 16) + lrow) * RS + lgrp * 16u;
#pragma unroll
        for (int ks = 0; ks < 6; ks++) {
            ldsm4(qH[ks], sb + aOff + (uint32_t)ks * 32u);
            ldsm4(qL[ks], sb + 26624u + aOff + (uint32_t)ks * 32u);
        }
        __syncthreads();
    }

    float m0 = NEG_INF, m1 = NEG_INF;
    float lp0 = 0.f, lp1 = 0.f;          // lane-partial l (quad-reduce at end)
    float o[12][4];
#pragma unroll
    for (int j = 0; j < 12; j++)
#pragma unroll
        for (int q = 0; q < 4; q++) o[j][q] = 0.f;

    auto produce = [&](int t) {
        const uint32_t base = sb + (uint32_t)(t & 1) * STG;
        const size_t gbase = ((size_t)bh * SEQ + t * 64) * HDIM;
        const char* kh = (const char*)(g_kh + gbase);
        const char* kl = (const char*)(g_kl + gbase);
        const char* vh = (const char*)(g_vh + gbase);
        const char* vl = (const char*)(g_vl + gbase);
#pragma unroll
        for (int i = 0; i < 6; i++) {
            int idx = tid + i * 128;
            int r = idx / 12, g = idx % 12;
            uint32_t so = (uint32_t)r * RS + (uint32_t)g * 16u;
            int go = r * 192 + g * 16;
            cp16(base + so,            kh + go);
            cp16(base + BSZ + so,      kl + go);
            cp16(base + 2u*BSZ + so,   vh + go);
            cp16(base + 3u*BSZ + so,   vl + go);
        }
        cp_commit();
    };

    produce(0);

    for (int t = 0; t < NTT; t++) {
        cp_wait<0>();
        __syncthreads();
        if (t + 1 < NTT) produce(t + 1);

        const uint32_t base = sb + (uint32_t)(t & 1) * STG;

        // ---- S = Q K^T (64x64 per CTA; this warp: 16 rows) ----
        float sacc[8][4];
#pragma unroll
        for (int j = 0; j < 8; j++)
#pragma unroll
            for (int q = 0; q < 4; q++) sacc[j][q] = 0.f;

#pragma unroll
        for (int ks = 0; ks < 6; ks++) {
            const uint32_t kb = (uint32_t)ks * 32u;
#pragma unroll
            for (int n2 = 0; n2 < 4; n2++) {
                const uint32_t bo = ((uint32_t)(n2 * 16) + lrow) * RS + lgrp * 16u + kb;
                uint32_t Bh4[4], Bl4[4];
                ldsm4(Bh4, base + bo);
                ldsm4(Bl4, base + BSZ + bo);
                uint32_t bh0[2] = {Bh4[0], Bh4[2]}, bh1[2] = {Bh4[1], Bh4[3]};
                uint32_t bl0[2] = {Bl4[0], Bl4[2]}, bl1[2] = {Bl4[1], Bl4[3]};
                mma_bf16(sacc[2*n2],   qH[ks], bh0);
                mma_bf16(sacc[2*n2],   qH[ks], bl0);
                mma_bf16(sacc[2*n2],   qL[ks], bh0);
                mma_bf16(sacc[2*n2+1], qH[ks], bh1);
                mma_bf16(sacc[2*n2+1], qH[ks], bl1);
                mma_bf16(sacc[2*n2+1], qL[ks], bh1);
            }
        }

        // ---- online softmax (base-2 domain), lane-partial l ----
        float mx0 = NEG_INF, mx1 = NEG_INF;
#pragma unroll
        for (int j = 0; j < 8; j++) {
            mx0 = fmaxf(mx0, fmaxf(sacc[j][0], sacc[j][1]));
            mx1 = fmaxf(mx1, fmaxf(sacc[j][2], sacc[j][3]));
        }
        mx0 = fmaxf(mx0, __shfl_xor_sync(0xffffffffu, mx0, 1));
        mx0 = fmaxf(mx0, __shfl_xor_sync(0xffffffffu, mx0, 2));
        mx1 = fmaxf(mx1, __shfl_xor_sync(0xffffffffu, mx1, 1));
        mx1 = fmaxf(mx1, __shfl_xor_sync(0xffffffffu, mx1, 2));
        float mn0 = fmaxf(m0, mx0), mn1 = fmaxf(m1, mx1);
        float c0 = ex2(m0 - mn0), c1 = ex2(m1 - mn1);
        m0 = mn0; m1 = mn1;
        float s0 = 0.f, s1 = 0.f;
#pragma unroll
        for (int j = 0; j < 8; j++) {
            float p0 = ex2(sacc[j][0] - mn0);
            float p1 = ex2(sacc[j][1] - mn0);
            float p2 = ex2(sacc[j][2] - mn1);
            float p3 = ex2(sacc[j][3] - mn1);
            sacc[j][0] = p0; sacc[j][1] = p1; sacc[j][2] = p2; sacc[j][3] = p3;
            s0 += p0 + p1; s1 += p2 + p3;
        }
        lp0 = lp0 * c0 + s0;    // c is quad-uniform -> lane partials reduce at end
        lp1 = lp1 * c1 + s1;

#pragma unroll
        for (int j = 0; j < 12; j++) {
            o[j][0] *= c0; o[j][1] *= c0; o[j][2] *= c1; o[j][3] *= c1;
        }

        // ---- O += P V ----
#pragma unroll
        for (int k2 = 0; k2 < 4; k2++) {
            uint32_t aH[4], aL[4];
            const int ta = 2 * k2, tb = 2 * k2 + 1;
            aH[0] = hi_pair(sacc[ta][0], sacc[ta][1]);
            aH[1] = hi_pair(sacc[ta][2], sacc[ta][3]);
            aH[2] = hi_pair(sacc[tb][0], sacc[tb][1]);
            aH[3] = hi_pair(sacc[tb][2], sacc[tb][3]);
            aL[0] = lo_pair(sacc[ta][0], sacc[ta][1]);
            aL[1] = lo_pair(sacc[ta][2], sacc[ta][3]);
            aL[2] = lo_pair(sacc[tb][0], sacc[tb][1]);
            aL[3] = lo_pair(sacc[tb][2], sacc[tb][3]);
#pragma unroll
            for (int dg = 0; dg < 6; dg++) {
                const uint32_t vo = ((uint32_t)(k2 * 16) + lrow) * RS + (uint32_t)dg * 32u + lgrp * 16u;
                uint32_t Vh4[4], Vl4[4];
                ldsm4t(Vh4, base + 2u*BSZ + vo);
                ldsm4t(Vl4, base + 3u*BSZ + vo);
                uint32_t vh0[2] = {Vh4[0], Vh4[1]}, vh1[2] = {Vh4[2], Vh4[3]};
                uint32_t vl0[2] = {Vl4[0], Vl4[1]}, vl1[2] = {Vl4[2], Vl4[3]};
                mma_bf16(o[2*dg],   aH, vh0);
                mma_bf16(o[2*dg],   aH, vl0);
                mma_bf16(o[2*dg],   aL, vh0);
                mma_bf16(o[2*dg+1], aH, vh1);
                mma_bf16(o[2*dg+1], aH, vl1);
                mma_bf16(o[2*dg+1], aL, vh1);
            }
        }
    }

    // ---- final l reduction (deferred), then epilogue ----
    float l0 = lp0, l1 = lp1;
    l0 += __shfl_xor_sync(0xffffffffu, l0, 1);
    l0 += __shfl_xor_sync(0xffffffffu, l0, 2);
    l1 += __shfl_xor_sync(0xffffffffu, l1, 1);
    l1 += __shfl_xor_sync(0xffffffffu, l1, 2);

    const int h = bh & (NH - 1), b = bh >> 3;
    const float i0 = 1.f / l0, i1 = 1.f / l1;
    const int r0 = q0 + wid * 16 + (lane >> 2);
    size_t base0 = ((size_t)b * SEQ + r0) * CH + h * HDIM + (lane & 3) * 2;
    size_t base1 = base0 + (size_t)8 * CH;
#pragma unroll
    for (int j = 0; j < 12; j++) {
        float a0 = o[j][0] * i0, a1 = o[j][1] * i0;
        float b0 = o[j][2] * i1, b1 = o[j][3] * i1;
        *(uint32_t*)(g_ch + base0 + j * 8) = hi_pair(a0, a1);
        *(uint32_t*)(g_cl + base0 + j * 8) = lo_pair(a0, a1);
        *(uint32_t*)(g_ch + base1 + j * 8) = hi_pair(b0, b1);
        *(uint32_t*)(g_cl + base1 + j * 8) = lo_pair(b0, b1);
    }
}

// ------------------------------ launch ---------------------------------------
extern "C" void kernel_launch(void* const* d_in, const int* in_sizes, int n_in,
                              void* d_out, int out_size)
{
    const float* x     = (const float*)d_in[0];
    const float* cosb  = (const float*)d_in[1];
    const float* sinb  = (const float*)d_in[2];
    const float* Wqkv  = (const float*)d_in[3];
    const float* Wproj = (const float*)d_in[4];
    const float* bproj = (const float*)d_in[5];
    float* out = (float*)d_out;

    const size_t shm_gemm = 3 * 32768;   // 98,304 B -> 2 CTAs/SM (BN=128)
    cudaFuncSetAttribute((gemm_bf16<0,128>), cudaFuncAttributeMaxDynamicSharedMemorySize, (int)shm_gemm);
    cudaFuncSetAttribute((gemm_bf16<1,128>), cudaFuncAttributeMaxDynamicSharedMemorySize, (int)shm_gemm);
    const size_t shm_flash = 2 * 53248;  // 106,496 B -> 2 CTAs/SM
    cudaFuncSetAttribute(flash_hmma, cudaFuncAttributeMaxDynamicSharedMemorySize, (int)shm_flash);

    // 0) split x, Wqkv, Wproj -> bf16 hi/lo
    {
        int quads = (MTOT*CH + N1*CH + CH*CH) / 4;
        split_all<<<(quads + 255) / 256, 256>>>(x, Wqkv, Wproj);
    }

    // 1) qkv GEMM + fused rope scatter (8192 x 2304, K=768), tile 128x128
    {
        __nv_bfloat16 *xh, *xl, *wqh, *wql;
        cudaGetSymbolAddress((void**)&xh,  g_xh);
        cudaGetSymbolAddress((void**)&xl,  g_xl);
        cudaGetSymbolAddress((void**)&wqh, g_wqh);
        cudaGetSymbolAddress((void**)&wql, g_wql);
        dim3 g1(N1 / 128, MTOT / 128);
        gemm_bf16<0,128><<<g1, 256, shm_gemm>>>(xh, xl, wqh, wql, cosb, sinb, nullptr, N1, CH);
    }

    // 2) flash attention (HMMA, 2 CTAs/SM) -> split ctx
    {
        dim3 g2(SEQ / 64, Bq * NH);
        flash_hmma<<<g2, 128, shm_flash>>>();
    }

    // 3) out = ctx @ Wproj^T + bproj (8192 x 768, K=768), tile 128x128
    {
        __nv_bfloat16 *ch, *cl, *wph, *wpl;
        cudaGetSymbolAddress((void**)&ch,  g_ch);
        cudaGetSymbolAddress((void**)&cl,  g_cl);
        cudaGetSymbolAddress((void**)&wph, g_wph);
        cudaGetSymbolAddress((void**)&wpl, g_wpl);
        dim3 g3(CH / 128, MTOT / 128);
        gemm_bf16<1,128><<<g3, 256, shm_gemm>>>(ch, cl, wph, wpl, bproj, nullptr, out, CH, CH);
    }
}

// round 17
// speedup vs baseline: 1.0122x; 1.0122x over previous
#include <cuda_runtime.h>
#include <cuda_bf16.h>
#include <cstdint>

#define Bq   4
#define SEQ  2048
#define CH   768
#define NH   8
#define HDIM 96
#define MTOT (Bq*SEQ)     /* 8192 */
#define N1   (3*CH)       /* 2304 */

// ---- HMMA helpers (baseline PTX, sm_80+) -------------------------------------
__device__ __forceinline__ uint32_t smem_u32(const void* p) {
    uint32_t a;
    asm("{ .reg .u64 t; cvta.to.shared.u64 t, %1; cvt.u32.u64 %0, t; }" : "=r"(a) : "l"(p));
    return a;
}
__device__ __forceinline__ void ldsm4(uint32_t* r, uint32_t addr) {
    asm volatile("ldmatrix.sync.aligned.m8n8.x4.shared.b16 {%0,%1,%2,%3}, [%4];"
        : "=r"(r[0]), "=r"(r[1]), "=r"(r[2]), "=r"(r[3]) : "r"(addr));
}
__device__ __forceinline__ void ldsm4t(uint32_t* r, uint32_t addr) {
    asm volatile("ldmatrix.sync.aligned.m8n8.x4.trans.shared.b16 {%0,%1,%2,%3}, [%4];"
        : "=r"(r[0]), "=r"(r[1]), "=r"(r[2]), "=r"(r[3]) : "r"(addr));
}
__device__ __forceinline__ void mma_bf16(float* d, const uint32_t* a, const uint32_t* b) {
    asm volatile("mma.sync.aligned.m16n8k16.row.col.f32.bf16.bf16.f32 "
        "{%0,%1,%2,%3}, {%4,%5,%6,%7}, {%8,%9}, {%0,%1,%2,%3};"
        : "+f"(d[0]), "+f"(d[1]), "+f"(d[2]), "+f"(d[3])
        : "r"(a[0]), "r"(a[1]), "r"(a[2]), "r"(a[3]), "r"(b[0]), "r"(b[1]));
}
__device__ __forceinline__ uint32_t hi_pair(float x, float y) {
    return __byte_perm(__float_as_uint(x), __float_as_uint(y), 0x7632);
}
__device__ __forceinline__ uint32_t lo_pair(float x, float y) {
    float lx = x - __uint_as_float(__float_as_uint(x) & 0xffff0000u);
    float ly = y - __uint_as_float(__float_as_uint(y) & 0xffff0000u);
    uint32_t r;
    asm("cvt.rn.bf16x2.f32 %0, %1, %2;" : "=r"(r) : "f"(ly), "f"(lx));
    return r;
}
__device__ __forceinline__ float ex2(float x) {
    float y; asm("ex2.approx.f32 %0, %1;" : "=f"(y) : "f"(x)); return y;
}
// ---- cp.async -----------------------------------------------------------------
__device__ __forceinline__ void cp16(uint32_t saddr, const void* g) {
    asm volatile("cp.async.cg.shared.global [%0], [%1], 16;" :: "r"(saddr), "l"(g));
}
__device__ __forceinline__ void cp_commit() { asm volatile("cp.async.commit_group;" ::: "memory"); }
template<int N> __device__ __forceinline__ void cp_wait() {
    asm volatile("cp.async.wait_group %0;" :: "n"(N) : "memory");
}

// ---------------- scratch (static __device__, no allocations) ----------------
__device__ __nv_bfloat16 g_xh[(size_t)MTOT*CH],  g_xl[(size_t)MTOT*CH];
__device__ __nv_bfloat16 g_wqh[(size_t)N1*CH],   g_wql[(size_t)N1*CH];
__device__ __nv_bfloat16 g_wph[(size_t)CH*CH],   g_wpl[(size_t)CH*CH];
__device__ __nv_bfloat16 g_qh[(size_t)Bq*NH*SEQ*HDIM];
__device__ __nv_bfloat16 g_ql[(size_t)Bq*NH*SEQ*HDIM];
__device__ __nv_bfloat16 g_kh[(size_t)Bq*NH*SEQ*HDIM];
__device__ __nv_bfloat16 g_kl[(size_t)Bq*NH*SEQ*HDIM];
__device__ __nv_bfloat16 g_vh[(size_t)Bq*NH*SEQ*HDIM];
__device__ __nv_bfloat16 g_vl[(size_t)Bq*NH*SEQ*HDIM];
__device__ __nv_bfloat16 g_ch[(size_t)MTOT*CH],  g_cl[(size_t)MTOT*CH];

// ---------------- split inputs once: fp32 -> bf16 hi/lo ----------------------
__global__ void split_all(const float* __restrict__ x,
                          const float* __restrict__ wq,
                          const float* __restrict__ wp)
{
    const int NX = MTOT*CH/4, NQ = N1*CH/4, NP = CH*CH/4;
    int i = blockIdx.x * blockDim.x + threadIdx.x;
    const float* src; __nv_bfloat16 *dh, *dl; int j;
    if (i < NX)                { src = x;  dh = g_xh;  dl = g_xl;  j = i; }
    else if (i < NX + NQ)      { src = wq; dh = g_wqh; dl = g_wql; j = i - NX; }
    else if (i < NX + NQ + NP) { src = wp; dh = g_wph; dl = g_wpl; j = i - NX - NQ; }
    else return;
    float4 v = ((const float4*)src)[j];
    uint2 hi = make_uint2(hi_pair(v.x, v.y), hi_pair(v.z, v.w));
    uint2 lo = make_uint2(lo_pair(v.x, v.y), lo_pair(v.z, v.w));
    ((uint2*)dh)[j] = hi;
    ((uint2*)dl)[j] = lo;
}

// ---------------- bf16-input HMMA NT GEMM, cp.async 3-stage, occ 2 ------------
__device__ __forceinline__ uint32_t swz(int r, int c) {   // byte offset of 16B chunk
    return (uint32_t)(r * 64 + ((c ^ ((r >> 1) & 3)) << 4));
}

template<int EPI>
__global__ __launch_bounds__(256, 2) void gemm_bf16(const __nv_bfloat16* __restrict__ Ah_g,
                                                    const __nv_bfloat16* __restrict__ Al_g,
                                                    const __nv_bfloat16* __restrict__ Bh_g,
                                                    const __nv_bfloat16* __restrict__ Bl_g,
                                                    const float* __restrict__ aux0,   // cos | bias
                                                    const float* __restrict__ aux1,   // sin | null
                                                    float* __restrict__ Cmat,
                                                    int Ntot, int Ktot)
{
    extern __shared__ __align__(128) char smem[];
    const uint32_t sb = smem_u32(smem);
    const int tid = threadIdx.x, wid = tid >> 5, lane = tid & 31;
    const int wm = (wid & 3) * 32;
    const int wn = (wid >> 2) * 64;
    const int m0 = blockIdx.y * 128, n0 = blockIdx.x * 128;

    float acc[2][8][4];
#pragma unroll
    for (int t = 0; t < 2; t++)
#pragma unroll
        for (int j = 0; j < 8; j++)
#pragma unroll
            for (int q = 0; q < 4; q++) acc[t][j][q] = 0.f;

    const int NIT = Ktot >> 5;   // 24
    const int chR = tid >> 2, chC = tid & 3;

    auto produce = [&](int it) {
        const uint32_t base = sb + (uint32_t)(it % 3) * 32768u;
        const int k0 = it << 5;
#pragma unroll
        for (int u = 0; u < 2; u++) {
            int r = chR + u * 64;
            uint32_t sw = swz(r, chC);
            size_t goA = (size_t)(m0 + r) * Ktot + k0 + chC * 8;
            size_t goB = (size_t)(n0 + r) * Ktot + k0 + chC * 8;
            cp16(base + sw,          Ah_g + goA);
            cp16(base + 8192u + sw,  Al_g + goA);
            cp16(base + 16384u + sw, Bh_g + goB);
            cp16(base + 24576u + sw, Bl_g + goB);
        }
        cp_commit();
    };

    const int lrow = lane & 15, lgrp = lane >> 4;

    auto compute = [&](int stg) {
        const uint32_t base = sb + (uint32_t)stg * 32768u;
#pragma unroll
        for (int ks = 0; ks < 2; ks++) {
            const int c = 2 * ks + lgrp;
            uint32_t Ahf[2][4], Alf[2][4];
#pragma unroll
            for (int t = 0; t < 2; t++) {
                int r = wm + t * 16 + lrow;
                uint32_t sw = swz(r, c);
                ldsm4(Ahf[t], base + sw);
                ldsm4(Alf[t], base + 8192u + sw);
            }
#pragma unroll
            for (int ng = 0; ng < 4; ng++) {
                int r = wn + ng * 16 + lrow;
                uint32_t sw = swz(r, c);
                uint32_t Bh4[4], Bl4[4];
                ldsm4(Bh4, base + 16384u + sw);
                ldsm4(Bl4, base + 24576u + sw);
                uint32_t bh0[2] = {Bh4[0], Bh4[2]}, bh1[2] = {Bh4[1], Bh4[3]};
                uint32_t bl0[2] = {Bl4[0], Bl4[2]}, bl1[2] = {Bl4[1], Bl4[3]};
#pragma unroll
                for (int t = 0; t < 2; t++) {
                    mma_bf16(acc[t][2*ng],   Ahf[t], bh0);
                    mma_bf16(acc[t][2*ng],   Ahf[t], bl0);
                    mma_bf16(acc[t][2*ng],   Alf[t], bh0);
                    mma_bf16(acc[t][2*ng+1], Ahf[t], bh1);
                    mma_bf16(acc[t][2*ng+1], Ahf[t], bl1);
                    mma_bf16(acc[t][2*ng+1], Alf[t], bh1);
                }
            }
        }
    };

    produce(0); produce(1);
    for (int it = 0; it < NIT; it++) {
        cp_wait<1>();
        __syncthreads();
        if (it + 2 < NIT) produce(it + 2);
        compute(it % 3);
    }

    // ---- epilogue ----
    if (EPI == 1) {
#pragma unroll
        for (int t = 0; t < 2; t++) {
            const int row0 = m0 + wm + t*16 + (lane >> 2);
#pragma unroll
            for (int j = 0; j < 8; j++) {
                const int col = n0 + wn + j*8 + (lane & 3)*2;
                float b0 = aux0[col], b1 = aux0[col+1];
                *(float2*)(Cmat + (size_t)row0 * Ntot + col) =
                    make_float2(acc[t][j][0] + b0, acc[t][j][1] + b1);
                *(float2*)(Cmat + (size_t)(row0+8) * Ntot + col) =
                    make_float2(acc[t][j][2] + b0, acc[t][j][3] + b1);
            }
        }
    } else {
        // q pre-scale folds HD^-0.5 AND log2(e) so flash can use raw ex2
        const float qscale = 0.10206207261596575f * 1.4426950408889634f;
#pragma unroll
        for (int t = 0; t < 2; t++) {
            const int rowA = m0 + wm + t*16 + (lane >> 2);
#pragma unroll
            for (int j = 0; j < 8; j++) {
                const int col = n0 + wn + j*8 + (lane & 3)*2;   // even
                const int which = col / CH;
                const int cc = col - which * CH;
                const int h = cc / HDIM;
                const int d = cc - h * HDIM;
#pragma unroll
                for (int half = 0; half < 2; half++) {
                    const int m = rowA + half * 8;
                    const int s = m & (SEQ - 1), b = m >> 11;
                    float e = acc[t][j][2*half], o = acc[t][j][2*half+1];
                    float2 y;
                    if (which == 2) {
                        y = make_float2(e, o);
                    } else {
                        float cs = aux0[s * HDIM + d];
                        float sn = aux1[s * HDIM + d];
                        y.x = e * cs - o * sn;
                        y.y = o * cs + e * sn;
                        if (which == 0) { y.x *= qscale; y.y *= qscale; }
                    }
                    size_t off = ((size_t)(b * NH + h) * SEQ + s) * HDIM + d;
                    uint32_t hi = hi_pair(y.x, y.y);
                    uint32_t lo = lo_pair(y.x, y.y);
                    __nv_bfloat16* dh = (which == 0) ? g_qh : (which == 1) ? g_kh : g_vh;
                    __nv_bfloat16* dl = (which == 0) ? g_ql : (which == 1) ? g_kl : g_vl;
                    *(uint32_t*)(dh + off) = hi;
                    *(uint32_t*)(dl + off) = lo;
                }
            }
        }
    }
}

// ---------------- flash attention: BM=64, BN=64, 4 warps, 2 CTAs/SM -----------
// (exact R12 structure — verified 790.5 us total; full 3-term PV)
#define RS   208u
#define BSZ  13312u
#define STG  53248u
#define NTT  32
__global__ __launch_bounds__(128, 2) void flash_hmma()
{
    extern __shared__ __align__(128) char sm[];
    const uint32_t sb = smem_u32(sm);

    const int tid = threadIdx.x, wid = tid >> 5, lane = tid & 31;
    const int bh = blockIdx.y;
    const int q0 = blockIdx.x * 64;
    const float NEG_INF = __int_as_float(0xff800000);

    const uint32_t lrow = (uint32_t)(lane & 15);
    const uint32_t lgrp = (uint32_t)(lane >> 4);

    // ---- stage Q (64 rows) into stage-0 area, ldsm to registers ----
    uint32_t qH[6][4], qL[6][4];
    {
        const char* qh = (const char*)(g_qh + ((size_t)bh * SEQ + q0) * HDIM);
        const char* ql = (const char*)(g_ql + ((size_t)bh * SEQ + q0) * HDIM);
#pragma unroll
        for (int i = 0; i < 6; i++) {
            int idx = tid + i * 128;            // 0..767 = 64 rows x 12 groups
            int r = idx / 12, g = idx % 12;
            uint32_t so = (uint32_t)r * RS + (uint32_t)g * 16u;
            *(uint4*)(sm + so)          = *(const uint4*)(qh + r * 192 + g * 16);
            *(uint4*)(sm + 26624u + so) = *(const uint4*)(ql + r * 192 + g * 16);
        }
        __syncthreads();
        const uint32_t aOff = ((uint32_t)(wid * 16) + lrow) * RS + lgrp * 16u;
#pragma unroll
        for (int ks = 0; ks < 6; ks++) {
            ldsm4(qH[ks], sb + aOff + (uint32_t)ks * 32u);
            ldsm4(qL[ks], sb + 26624u + aOff + (uint32_t)ks * 32u);
        }
        __syncthreads();   // all warps done reading stage-0 before produce(0)
    }

    float m0 = NEG_INF, m1 = NEG_INF, l0 = 0.f, l1 = 0.f;
    float o[12][4];
#pragma unroll
    for (int j = 0; j < 12; j++)
#pragma unroll
        for (int q = 0; q < 4; q++) o[j][q] = 0.f;

    auto produce = [&](int t) {
        const uint32_t base = sb + (uint32_t)(t & 1) * STG;
        const size_t gbase = ((size_t)bh * SEQ + t * 64) * HDIM;
        const char* kh = (const char*)(g_kh + gbase);
        const char* kl = (const char*)(g_kl + gbase);
        const char* vh = (const char*)(g_vh + gbase);
        const char* vl = (const char*)(g_vl + gbase);
#pragma unroll
        for (int i = 0; i < 6; i++) {
            int idx = tid + i * 128;
            int r = idx / 12, g = idx % 12;
            uint32_t so = (uint32_t)r * RS + (uint32_t)g * 16u;
            int go = r * 192 + g * 16;
            cp16(base + so,            kh + go);
            cp16(base + BSZ + so,      kl + go);
            cp16(base + 2u*BSZ + so,   vh + go);
            cp16(base + 3u*BSZ + so,   vl + go);
        }
        cp_commit();
    };

    produce(0);

    for (int t = 0; t < NTT; t++) {
        cp_wait<0>();
        __syncthreads();
        if (t + 1 < NTT) produce(t + 1);

        const uint32_t base = sb + (uint32_t)(t & 1) * STG;

        // ---- S = Q K^T (64x64 per CTA; this warp: 16 rows) ----
        float sacc[8][4];
#pragma unroll
        for (int j = 0; j < 8; j++)
#pragma unroll
            for (int q = 0; q < 4; q++) sacc[j][q] = 0.f;

#pragma unroll
        for (int ks = 0; ks < 6; ks++) {
            const uint32_t kb = (uint32_t)ks * 32u;
#pragma unroll
            for (int n2 = 0; n2 < 4; n2++) {
                const uint32_t bo = ((uint32_t)(n2 * 16) + lrow) * RS + lgrp * 16u + kb;
                uint32_t Bh4[4], Bl4[4];
                ldsm4(Bh4, base + bo);
                ldsm4(Bl4, base + BSZ + bo);
                uint32_t bh0[2] = {Bh4[0], Bh4[2]}, bh1[2] = {Bh4[1], Bh4[3]};
                uint32_t bl0[2] = {Bl4[0], Bl4[2]}, bl1[2] = {Bl4[1], Bl4[3]};
                mma_bf16(sacc[2*n2],   qH[ks], bh0);
                mma_bf16(sacc[2*n2],   qH[ks], bl0);
                mma_bf16(sacc[2*n2],   qL[ks], bh0);
                mma_bf16(sacc[2*n2+1], qH[ks], bh1);
                mma_bf16(sacc[2*n2+1], qH[ks], bl1);
                mma_bf16(sacc[2*n2+1], qL[ks], bh1);
            }
        }

        // ---- online softmax in registers (base-2 domain) ----
        float mx0 = NEG_INF, mx1 = NEG_INF;
#pragma unroll
        for (int j = 0; j < 8; j++) {
            mx0 = fmaxf(mx0, fmaxf(sacc[j][0], sacc[j][1]));
            mx1 = fmaxf(mx1, fmaxf(sacc[j][2], sacc[j][3]));
        }
        mx0 = fmaxf(mx0, __shfl_xor_sync(0xffffffffu, mx0, 1));
        mx0 = fmaxf(mx0, __shfl_xor_sync(0xffffffffu, mx0, 2));
        mx1 = fmaxf(mx1, __shfl_xor_sync(0xffffffffu, mx1, 1));
        mx1 = fmaxf(mx1, __shfl_xor_sync(0xffffffffu, mx1, 2));
        float mn0 = fmaxf(m0, mx0), mn1 = fmaxf(m1, mx1);
        float c0 = ex2(m0 - mn0), c1 = ex2(m1 - mn1);
        m0 = mn0; m1 = mn1;
        float s0 = 0.f, s1 = 0.f;
#pragma unroll
        for (int j = 0; j < 8; j++) {
            float p0 = ex2(sacc[j][0] - mn0);
            float p1 = ex2(sacc[j][1] - mn0);
            float p2 = ex2(sacc[j][2] - mn1);
            float p3 = ex2(sacc[j][3] - mn1);
            sacc[j][0] = p0; sacc[j][1] = p1; sacc[j][2] = p2; sacc[j][3] = p3;
            s0 += p0 + p1; s1 += p2 + p3;
        }
        s0 += __shfl_xor_sync(0xffffffffu, s0, 1);
        s0 += __shfl_xor_sync(0xffffffffu, s0, 2);
        s1 += __shfl_xor_sync(0xffffffffu, s1, 1);
        s1 += __shfl_xor_sync(0xffffffffu, s1, 2);
        l0 = l0 * c0 + s0;
        l1 = l1 * c1 + s1;

#pragma unroll
        for (int j = 0; j < 12; j++) {
            o[j][0] *= c0; o[j][1] *= c0; o[j][2] *= c1; o[j][3] *= c1;
        }

        // ---- O += P V (full 3-term) ----
#pragma unroll
        for (int k2 = 0; k2 < 4; k2++) {
            uint32_t aH[4], aL[4];
            const int ta = 2 * k2, tb = 2 * k2 + 1;
            aH[0] = hi_pair(sacc[ta][0], sacc[ta][1]);
            aH[1] = hi_pair(sacc[ta][2], sacc[ta][3]);
            aH[2] = hi_pair(sacc[tb][0], sacc[tb][1]);
            aH[3] = hi_pair(sacc[tb][2], sacc[tb][3]);
            aL[0] = lo_pair(sacc[ta][0], sacc[ta][1]);
            aL[1] = lo_pair(sacc[ta][2], sacc[ta][3]);
            aL[2] = lo_pair(sacc[tb][0], sacc[tb][1]);
            aL[3] = lo_pair(sacc[tb][2], sacc[tb][3]);
#pragma unroll
            for (int dg = 0; dg < 6; dg++) {
                const uint32_t vo = ((uint32_t)(k2 * 16) + lrow) * RS + (uint32_t)dg * 32u + lgrp * 16u;
                uint32_t Vh4[4], Vl4[4];
                ldsm4t(Vh4, base + 2u*BSZ + vo);
                ldsm4t(Vl4, base + 3u*BSZ + vo);
                uint32_t vh0[2] = {Vh4[0], Vh4[1]}, vh1[2] = {Vh4[2], Vh4[3]};
                uint32_t vl0[2] = {Vl4[0], Vl4[1]}, vl1[2] = {Vl4[2], Vl4[3]};
                mma_bf16(o[2*dg],   aH, vh0);
                mma_bf16(o[2*dg],   aH, vl0);
                mma_bf16(o[2*dg],   aL, vh0);
                mma_bf16(o[2*dg+1], aH, vh1);
                mma_bf16(o[2*dg+1], aH, vl1);
                mma_bf16(o[2*dg+1], aL, vh1);
            }
        }
    }

    // ---- epilogue: ctx split bf16: (b, s, h*96 + d) ----
    const int h = bh & (NH - 1), b = bh >> 3;
    const float i0 = 1.f / l0, i1 = 1.f / l1;
    const int r0 = q0 + wid * 16 + (lane >> 2);
    size_t base0 = ((size_t)b * SEQ + r0) * CH + h * HDIM + (lane & 3) * 2;
    size_t base1 = base0 + (size_t)8 * CH;
#pragma unroll
    for (int j = 0; j < 12; j++) {
        float a0 = o[j][0] * i0, a1 = o[j][1] * i0;
        float b0 = o[j][2] * i1, b1 = o[j][3] * i1;
        *(uint32_t*)(g_ch + base0 + j * 8) = hi_pair(a0, a1);
        *(uint32_t*)(g_cl + base0 + j * 8) = lo_pair(a0, a1);
        *(uint32_t*)(g_ch + base1 + j * 8) = hi_pair(b0, b1);
        *(uint32_t*)(g_cl + base1 + j * 8) = lo_pair(b0, b1);
    }
}

// ------------------------------ launch ---------------------------------------
extern "C" void kernel_launch(void* const* d_in, const int* in_sizes, int n_in,
                              void* d_out, int out_size)
{
    const float* x     = (const float*)d_in[0];
    const float* cosb  = (const float*)d_in[1];
    const float* sinb  = (const float*)d_in[2];
    const float* Wqkv  = (const float*)d_in[3];
    const float* Wproj = (const float*)d_in[4];
    const float* bproj = (const float*)d_in[5];
    float* out = (float*)d_out;

    const size_t shm_gemm = 3 * 32768;       // 98,304 B -> 2 CTAs/SM
    cudaFuncSetAttribute(gemm_bf16<0>, cudaFuncAttributeMaxDynamicSharedMemorySize, (int)shm_gemm);
    cudaFuncSetAttribute(gemm_bf16<1>, cudaFuncAttributeMaxDynamicSharedMemorySize, (int)shm_gemm);
    const size_t shm_flash = 2 * 53248;      // 106,496 B -> 2 CTAs/SM
    cudaFuncSetAttribute(flash_hmma, cudaFuncAttributeMaxDynamicSharedMemorySize, (int)shm_flash);

    // 0) split x, Wqkv, Wproj -> bf16 hi/lo
    {
        int quads = (MTOT*CH + N1*CH + CH*CH) / 4;
        split_all<<<(quads + 255) / 256, 256>>>(x, Wqkv, Wproj);
    }

    // 1) qkv GEMM + fused rope scatter (8192 x 2304, K=768)
    {
        __nv_bfloat16 *xh, *xl, *wqh, *wql;
        cudaGetSymbolAddress((void**)&xh,  g_xh);
        cudaGetSymbolAddress((void**)&xl,  g_xl);
        cudaGetSymbolAddress((void**)&wqh, g_wqh);
        cudaGetSymbolAddress((void**)&wql, g_wql);
        dim3 g1(N1 / 128, MTOT / 128);
        gemm_bf16<0><<<g1, 256, shm_gemm>>>(xh, xl, wqh, wql, cosb, sinb, nullptr, N1, CH);
    }

    // 2) flash attention (HMMA, 2 CTAs/SM) -> split ctx
    {
        dim3 g2(SEQ / 64, Bq * NH);
        flash_hmma<<<g2, 128, shm_flash>>>();
    }

    // 3) out = ctx @ Wproj^T + bproj (8192 x 768, K=768)
    {
        __nv_bfloat16 *ch, *cl, *wph, *wpl;
        cudaGetSymbolAddress((void**)&ch,  g_ch);
        cudaGetSymbolAddress((void**)&cl,  g_cl);
        cudaGetSymbolAddress((void**)&wph, g_wph);
        cudaGetSymbolAddress((void**)&wpl, g_wpl);
        dim3 g3(CH / 128, MTOT / 128);
        gemm_bf16<1><<<g3, 256, shm_gemm>>>(ch, cl, wph, wpl, bproj, nullptr, out, CH, CH);
    }
}